// round 15
// baseline (speedup 1.0000x reference)
#include <cuda_runtime.h>
#include <math.h>
#include <stdint.h>

// Problem constants
#define NN   100000
#define FIN  64
#define CC   128
#define HH   2
#define DD   64
#define EE   600000
#define MT   2
#define OUTD 8

// ---------------------------------------------------------------------------
// Scratch (device globals — no allocation allowed)
// ---------------------------------------------------------------------------
__device__ float    g_h[(size_t)NN * CC];
__device__ float    g_out[(size_t)MT * NN * CC];   // both edge-type outputs
__device__ float    g_asrc[MT * NN * HH];
__device__ float    g_adst[MT * NN * HH];
__device__ float    g_alpha[(size_t)MT * EE * HH];
__device__ float    g_asum[MT * NN * HH];
__device__ float    g_colsum[MT * CC];
__device__ float    g_attn[MT];

// ---------------------------------------------------------------------------
// Helpers
// ---------------------------------------------------------------------------
__device__ __forceinline__ float tanh_fast(float x) {
    float y;
    asm("tanh.approx.f32 %0, %1;" : "=f"(y) : "f"(x));
    return y;
}
__device__ __forceinline__ void red_add_v4(float* p, float x, float y, float z, float w) {
    asm volatile("red.global.add.v4.f32 [%0], {%1,%2,%3,%4};"
                 :: "l"(p), "f"(x), "f"(y), "f"(z), "f"(w) : "memory");
}
__device__ __forceinline__ void red_add_v2(float* p, float x, float y) {
    asm volatile("red.global.add.v2.f32 [%0], {%1,%2};"
                 :: "l"(p), "f"(x), "f"(y) : "memory");
}
__device__ __forceinline__ float f2tf32f(float f) {
    uint32_t u;
    asm("cvt.rna.tf32.f32 %0, %1;" : "=r"(u) : "f"(f));
    return __uint_as_float(u);
}
__device__ __forceinline__ void mma_tf32(float& c0, float& c1, float& c2, float& c3,
                                         uint32_t a0, uint32_t a1, uint32_t a2, uint32_t a3,
                                         uint32_t b0, uint32_t b1) {
    asm volatile(
        "mma.sync.aligned.m16n8k8.row.col.f32.tf32.tf32.f32 "
        "{%0,%1,%2,%3}, {%4,%5,%6,%7}, {%8,%9}, {%0,%1,%2,%3};"
        : "+f"(c0), "+f"(c1), "+f"(c2), "+f"(c3)
        : "r"(a0), "r"(a1), "r"(a2), "r"(a3), "r"(b0), "r"(b1));
}

// ===========================================================================
// tf32 GEMM core layout (R10/R14 validated): 64x128 tile, fragment-major W.
// ===========================================================================

// ---------------------------------------------------------------------------
// tf32 projection GEMM (R14 WIN): out[n,c] = A[n,:K] @ W[K,128] + b[c]
// FUSED (layer-2): A row := attn0*relu(o0) + attn1*relu(o1)
// ---------------------------------------------------------------------------
template <int K, bool FUSED>
__global__ void __launch_bounds__(256)
proj_tf32_kernel(const float* __restrict__ A,
                 const float* __restrict__ A2,
                 const float* __restrict__ attn,
                 const float* __restrict__ W,
                 const float* __restrict__ b,
                 float* __restrict__ out) {
    extern __shared__ float smem[];
    float* sWf = smem;
    float* sA  = smem + K * 128;
    const int tid  = threadIdx.x;
    const int lane = tid & 31;
    const int warp = tid >> 5;
    const int g4   = lane >> 2;
    const int tig  = lane & 3;
    const int rt   = warp & 3;
    const int ch   = warp >> 2;
    const int KS = K + 4;

    for (int i4 = tid; i4 < K * 32; i4 += 256) {
        int k  = i4 >> 5;
        int n0 = (i4 & 31) * 4;
        float4 w4 = ((const float4*)W)[i4];
        float wv[4] = {w4.x, w4.y, w4.z, w4.w};
        int ks = k >> 3;
        int slot = (k & 7) >> 2;
        int km = k & 3;
#pragma unroll
        for (int j = 0; j < 4; ++j) {
            int n = n0 + j;
            int nt = n >> 3;
            int ln = (n & 7) * 4 + km;
            sWf[(((ks * 16) + nt) * 32 + ln) * 2 + slot] = f2tf32f(wv[j]);
        }
    }

    float2 bv[8];
#pragma unroll
    for (int nl = 0; nl < 8; ++nl)
        bv[nl] = *(const float2*)&b[(ch * 8 + nl) * 8 + tig * 2];

    float at0 = 0.f, at1 = 0.f;
    if (FUSED) { at0 = attn[0]; at1 = attn[1]; }

    const int ntiles = (NN + 63) / 64;
    for (int tile = blockIdx.x; tile < ntiles; tile += gridDim.x) {
        __syncthreads();
        const int rowbase = tile * 64;
        const float4* Ab  = (const float4*)(A  + (size_t)rowbase * K);
        const float4* Ab2 = FUSED ? (const float4*)(A2 + (size_t)rowbase * K)
                                  : nullptr;
        for (int i4 = tid; i4 < 64 * (K / 4); i4 += 256) {
            int r = i4 / (K / 4), k4 = i4 % (K / 4);
            float4 v = make_float4(0.f, 0.f, 0.f, 0.f);
            if (rowbase + r < NN) {
                if (FUSED) {
                    float4 u = Ab[i4], w = Ab2[i4];
                    v.x = f2tf32f(at0 * fmaxf(u.x, 0.f) + at1 * fmaxf(w.x, 0.f));
                    v.y = f2tf32f(at0 * fmaxf(u.y, 0.f) + at1 * fmaxf(w.y, 0.f));
                    v.z = f2tf32f(at0 * fmaxf(u.z, 0.f) + at1 * fmaxf(w.z, 0.f));
                    v.w = f2tf32f(at0 * fmaxf(u.w, 0.f) + at1 * fmaxf(w.w, 0.f));
                } else {
                    float4 u = Ab[i4];
                    v.x = f2tf32f(u.x); v.y = f2tf32f(u.y);
                    v.z = f2tf32f(u.z); v.w = f2tf32f(u.w);
                }
            }
            float* dst = &sA[r * KS + k4 * 4];
            dst[0] = v.x; dst[1] = v.y; dst[2] = v.z; dst[3] = v.w;
        }
        __syncthreads();

        float c[8][4];
#pragma unroll
        for (int nl = 0; nl < 8; ++nl)
#pragma unroll
            for (int j = 0; j < 4; ++j) c[nl][j] = 0.0f;

        const int abase = (rt * 16 + g4) * KS;
#pragma unroll 4
        for (int ks = 0; ks < K / 8; ++ks) {
            const int k0 = ks * 8;
            uint32_t a0 = __float_as_uint(sA[abase + k0 + tig]);
            uint32_t a1 = __float_as_uint(sA[abase + 8 * KS + k0 + tig]);
            uint32_t a2 = __float_as_uint(sA[abase + k0 + 4 + tig]);
            uint32_t a3 = __float_as_uint(sA[abase + 8 * KS + k0 + 4 + tig]);
#pragma unroll
            for (int nl = 0; nl < 8; ++nl) {
                int nt = ch * 8 + nl;
                float2 bf = *(const float2*)&sWf[((ks * 16 + nt) * 32 + lane) * 2];
                mma_tf32(c[nl][0], c[nl][1], c[nl][2], c[nl][3],
                         a0, a1, a2, a3,
                         __float_as_uint(bf.x), __float_as_uint(bf.y));
            }
        }

        const int rowa = rowbase + rt * 16 + g4;
        const int rowb = rowa + 8;
#pragma unroll
        for (int nl = 0; nl < 8; ++nl) {
            int col = (ch * 8 + nl) * 8 + tig * 2;
            if (rowa < NN)
                *(float2*)&out[(size_t)rowa * 128 + col] =
                    make_float2(c[nl][0] + bv[nl].x, c[nl][1] + bv[nl].y);
            if (rowb < NN)
                *(float2*)&out[(size_t)rowb * 128 + col] =
                    make_float2(c[nl][2] + bv[nl].x, c[nl][3] + bv[nl].y);
        }
    }
}

// ---------------------------------------------------------------------------
// Semantic GEMM, tf32, BOTH edge types in one launch:
// blocks [0,296) -> type 0, [296,592) -> type 1.
// colsum[t][c] += sum_n tanh( relu(out[t][n,:]) @ kw[:,c] + kb[c] )
// ---------------------------------------------------------------------------
#define GEMM_BLOCKS 296
#define SEM_TILES ((NN + 63) / 64)
__global__ void __launch_bounds__(256)
semantic_both_kernel(const float* __restrict__ outT,
                     const float* __restrict__ kw,
                     const float* __restrict__ kb,
                     float* __restrict__ colsum) {
    extern __shared__ float smem[];
    float* sWf = smem;
    float* sA  = smem + 16384;
    __shared__ float scol[128];
    const int tid  = threadIdx.x;
    const int lane = tid & 31;
    const int warp = tid >> 5;
    const int g4   = lane >> 2;
    const int tig  = lane & 3;
    const int rt   = warp & 3;
    const int ch   = warp >> 2;
    const int t    = blockIdx.x >= GEMM_BLOCKS;
    const float* A = outT + (size_t)t * NN * CC;
    float* cs      = colsum + t * CC;
    const int tile0 = blockIdx.x - t * GEMM_BLOCKS;

    for (int i4 = tid; i4 < 4096; i4 += 256) {
        int k  = i4 >> 5;
        int n0 = (i4 & 31) * 4;
        float4 w4 = ((const float4*)kw)[i4];
        float wv[4] = {w4.x, w4.y, w4.z, w4.w};
        int ks = k >> 3;
        int slot = (k & 7) >> 2;
        int km = k & 3;
#pragma unroll
        for (int j = 0; j < 4; ++j) {
            int n = n0 + j;
            int nt = n >> 3;
            int ln = (n & 7) * 4 + km;
            sWf[(((ks * 16) + nt) * 32 + ln) * 2 + slot] = f2tf32f(wv[j]);
        }
    }
    if (tid < 128) scol[tid] = 0.0f;

    float2 kbv[8];
#pragma unroll
    for (int nl = 0; nl < 8; ++nl)
        kbv[nl] = *(const float2*)&kb[(ch * 8 + nl) * 8 + tig * 2];

    float tloc[8][2];
#pragma unroll
    for (int nl = 0; nl < 8; ++nl) { tloc[nl][0] = 0.f; tloc[nl][1] = 0.f; }

    for (int tile = tile0; tile < SEM_TILES; tile += GEMM_BLOCKS) {
        __syncthreads();
        const int rowbase = tile * 64;
        const float4* Ab = (const float4*)(A + (size_t)rowbase * 128);
        for (int i4 = tid; i4 < 2048; i4 += 256) {
            int r = i4 >> 5, k4 = i4 & 31;
            float4 v = make_float4(0.f, 0.f, 0.f, 0.f);
            if (rowbase + r < NN) {
                float4 u = Ab[i4];
                v.x = f2tf32f(fmaxf(u.x, 0.f));
                v.y = f2tf32f(fmaxf(u.y, 0.f));
                v.z = f2tf32f(fmaxf(u.z, 0.f));
                v.w = f2tf32f(fmaxf(u.w, 0.f));
            }
            float* dst = &sA[r * 132 + k4 * 4];
            dst[0] = v.x; dst[1] = v.y; dst[2] = v.z; dst[3] = v.w;
        }
        __syncthreads();

        float c[8][4];
#pragma unroll
        for (int nl = 0; nl < 8; ++nl)
#pragma unroll
            for (int j = 0; j < 4; ++j) c[nl][j] = 0.0f;

        const int abase = (rt * 16 + g4) * 132;
#pragma unroll 4
        for (int ks = 0; ks < 16; ++ks) {
            const int k0 = ks * 8;
            uint32_t a0 = __float_as_uint(sA[abase + k0 + tig]);
            uint32_t a1 = __float_as_uint(sA[abase + 8 * 132 + k0 + tig]);
            uint32_t a2 = __float_as_uint(sA[abase + k0 + 4 + tig]);
            uint32_t a3 = __float_as_uint(sA[abase + 8 * 132 + k0 + 4 + tig]);
#pragma unroll
            for (int nl = 0; nl < 8; ++nl) {
                int nt = ch * 8 + nl;
                float2 bf = *(const float2*)&sWf[((ks * 16 + nt) * 32 + lane) * 2];
                mma_tf32(c[nl][0], c[nl][1], c[nl][2], c[nl][3],
                         a0, a1, a2, a3,
                         __float_as_uint(bf.x), __float_as_uint(bf.y));
            }
        }

        const int rowa = rowbase + rt * 16 + g4;
        const int rowb = rowa + 8;
        const bool va = rowa < NN, vb = rowb < NN;
#pragma unroll
        for (int nl = 0; nl < 8; ++nl) {
            if (va) {
                tloc[nl][0] += tanh_fast(c[nl][0] + kbv[nl].x);
                tloc[nl][1] += tanh_fast(c[nl][1] + kbv[nl].y);
            }
            if (vb) {
                tloc[nl][0] += tanh_fast(c[nl][2] + kbv[nl].x);
                tloc[nl][1] += tanh_fast(c[nl][3] + kbv[nl].y);
            }
        }
    }

#pragma unroll
    for (int nl = 0; nl < 8; ++nl) {
        int col = (ch * 8 + nl) * 8 + tig * 2;
        atomicAdd(&scol[col], tloc[nl][0]);
        atomicAdd(&scol[col + 1], tloc[nl][1]);
    }
    __syncthreads();
    if (tid < 128) atomicAdd(&cs[tid], scol[tid]);
}

// ---------------------------------------------------------------------------
// Per-node attention logits, warp per node
// ---------------------------------------------------------------------------
__global__ void node_attn_kernel(const float* __restrict__ h,
                                 const float* __restrict__ att_src,
                                 const float* __restrict__ att_dst,
                                 float* __restrict__ asrc,
                                 float* __restrict__ adst, int n) {
    int gid = blockIdx.x * blockDim.x + threadIdx.x;
    int node = gid >> 5;
    int lane = gid & 31;
    if (node >= n) return;
    const float* hrow = h + (size_t)node * CC;
    float h00 = hrow[lane];
    float h01 = hrow[lane + 32];
    float h10 = hrow[lane + 64];
    float h11 = hrow[lane + 96];

    float r[8];
#pragma unroll
    for (int t = 0; t < MT; ++t) {
        const float* as = att_src + t * CC;
        const float* ad = att_dst + t * CC;
        r[t * 4 + 0] = h00 * as[lane] + h01 * as[lane + 32];
        r[t * 4 + 1] = h10 * as[lane + 64] + h11 * as[lane + 96];
        r[t * 4 + 2] = h00 * ad[lane] + h01 * ad[lane + 32];
        r[t * 4 + 3] = h10 * ad[lane + 64] + h11 * ad[lane + 96];
    }
#pragma unroll
    for (int i = 0; i < 8; ++i) {
#pragma unroll
        for (int off = 16; off > 0; off >>= 1)
            r[i] += __shfl_xor_sync(0xffffffffu, r[i], off);
    }
    if (lane == 0) {
#pragma unroll
        for (int t = 0; t < MT; ++t) {
            asrc[t * (NN * HH) + node * HH + 0] = r[t * 4 + 0];
            asrc[t * (NN * HH) + node * HH + 1] = r[t * 4 + 1];
            adst[t * (NN * HH) + node * HH + 0] = r[t * 4 + 2];
            adst[t * (NN * HH) + node * HH + 1] = r[t * 4 + 3];
        }
    }
}

// ---------------------------------------------------------------------------
// Edge softmax, BOTH edge types in one launch (2E threads):
// alpha[t][e] = exp(leaky(asrc[t][src]+adst[t][dst])); asum[t][dst] += alpha
// ---------------------------------------------------------------------------
__global__ void edge_softmax_both(const int* __restrict__ ei0,
                                  const int* __restrict__ ei1,
                                  const float* __restrict__ asrc,
                                  const float* __restrict__ adst,
                                  float* __restrict__ alpha,
                                  float* __restrict__ asum) {
    int e2 = blockIdx.x * blockDim.x + threadIdx.x;
    if (e2 >= 2 * EE) return;
    int t = e2 >= EE;
    int e = e2 - t * EE;
    const int* ei = t ? ei1 : ei0;
    const float* as = asrc + t * (NN * HH);
    const float* ad = adst + t * (NN * HH);
    int src = ei[e];
    int dst = ei[EE + e];
    float2 s = *(const float2*)&as[src * HH];
    float2 d = *(const float2*)&ad[dst * HH];
    float a0 = s.x + d.x;
    float a1 = s.y + d.y;
    float l0 = (a0 > 0.0f) ? a0 : 0.2f * a0;
    float l1 = (a1 > 0.0f) ? a1 : 0.2f * a1;
    float ex0 = expf(l0);
    float ex1 = expf(l1);
    *(float2*)&alpha[((size_t)t * EE + e) * HH] = make_float2(ex0, ex1);
    red_add_v2(&asum[t * (NN * HH) + dst * HH], ex0, ex1);
}

// ---------------------------------------------------------------------------
// Edge message, BOTH types, 8 edges per warp (MLP ~24):
// out[t][dst] += h[src] * coef  via red.v4.  EE % 8 == 0.
// ---------------------------------------------------------------------------
__global__ void edge_message_both(const int* __restrict__ ei0,
                                  const int* __restrict__ ei1,
                                  const float* __restrict__ alpha,
                                  const float* __restrict__ asum,
                                  const float* __restrict__ h,
                                  float* __restrict__ outT) {
    int gid = blockIdx.x * blockDim.x + threadIdx.x;
    int w = gid >> 5;
    int lane = gid & 31;
    const int WPT = EE / 8;              // warps per type
    if (w >= 2 * WPT) return;
    int t = w >= WPT;
    int wl = w - t * WPT;
    const int* ei = t ? ei1 : ei0;
    const float* al = alpha + (size_t)t * EE * HH;
    const float* su = asum + t * (NN * HH);
    float* ot = outT + (size_t)t * NN * CC;
    const int e0 = wl * 8;
    const int head = lane >> 4;

    int4 sa = ((const int4*)ei)[wl * 2];
    int4 sb = ((const int4*)ei)[wl * 2 + 1];
    int4 da = ((const int4*)ei)[EE / 4 + wl * 2];
    int4 db = ((const int4*)ei)[EE / 4 + wl * 2 + 1];
    int srcs[8] = {sa.x, sa.y, sa.z, sa.w, sb.x, sb.y, sb.z, sb.w};
    int dsts[8] = {da.x, da.y, da.z, da.w, db.x, db.y, db.z, db.w};

    float av[8], sv[8];
#pragma unroll
    for (int i = 0; i < 8; ++i)
        av[i] = al[(size_t)(e0 + i) * HH + head];
#pragma unroll
    for (int i = 0; i < 8; ++i)
        sv[i] = su[dsts[i] * HH + head];

    float4 v[8];
#pragma unroll
    for (int i = 0; i < 8; ++i)
        v[i] = ((const float4*)(h + (size_t)srcs[i] * CC))[lane];

#pragma unroll
    for (int i = 0; i < 8; ++i) {
        float coef = av[i] / (sv[i] + 1e-16f);
        float* o = ot + (size_t)dsts[i] * CC + lane * 4;
        red_add_v4(o, v[i].x * coef, v[i].y * coef, v[i].z * coef, v[i].w * coef);
    }
}

// ---------------------------------------------------------------------------
// Semantic score + softmax (single block, 128 threads)
// ---------------------------------------------------------------------------
__global__ void score_softmax_kernel(const float* __restrict__ q,
                                     const float* __restrict__ colsum,
                                     float* __restrict__ attn) {
    __shared__ float red[128];
    int c = threadIdx.x;
    float s[MT];
#pragma unroll
    for (int m = 0; m < MT; ++m) {
        red[c] = q[c] * colsum[m * CC + c];
        __syncthreads();
        for (int off = 64; off > 0; off >>= 1) {
            if (c < off) red[c] += red[c + off];
            __syncthreads();
        }
        s[m] = red[0] * (1.0f / (float)NN);
        __syncthreads();
    }
    if (c == 0) {
        float mx = fmaxf(s[0], s[1]);
        float e0 = expf(s[0] - mx), e1 = expf(s[1] - mx);
        float inv = 1.0f / (e0 + e1);
        attn[0] = e0 * inv;
        attn[1] = e1 * inv;
    }
}

// ---------------------------------------------------------------------------
// Final linear fused with combine: warp per node
// ---------------------------------------------------------------------------
__global__ void final_linear_kernel(const float* __restrict__ o0,
                                    const float* __restrict__ o1,
                                    const float* __restrict__ attn,
                                    const float* __restrict__ lw,
                                    const float* __restrict__ lb,
                                    float* __restrict__ out) {
    int gid = blockIdx.x * blockDim.x + threadIdx.x;
    int node = gid >> 5;
    int lane = gid & 31;
    if (node >= NN) return;
    float a0 = attn[0], a1 = attn[1];
    float4 u = ((const float4*)(o0 + (size_t)node * CC))[lane];
    float4 v = ((const float4*)(o1 + (size_t)node * CC))[lane];
    float c0 = a0 * fmaxf(u.x, 0.f) + a1 * fmaxf(v.x, 0.f);
    float c1 = a0 * fmaxf(u.y, 0.f) + a1 * fmaxf(v.y, 0.f);
    float c2 = a0 * fmaxf(u.z, 0.f) + a1 * fmaxf(v.z, 0.f);
    float c3 = a0 * fmaxf(u.w, 0.f) + a1 * fmaxf(v.w, 0.f);
    const float* w = lw + lane * 4 * OUTD;
#pragma unroll
    for (int o = 0; o < OUTD; ++o) {
        float p = c0 * w[o] + c1 * w[OUTD + o] + c2 * w[2 * OUTD + o]
                + c3 * w[3 * OUTD + o];
#pragma unroll
        for (int off = 16; off > 0; off >>= 1)
            p += __shfl_xor_sync(0xffffffffu, p, off);
        if (lane == 0) out[(size_t)node * OUTD + o] = p + lb[o];
    }
}

// ---------------------------------------------------------------------------
// Host side
// ---------------------------------------------------------------------------
struct Scratch {
    float* h; float* out;
    float* asrc; float* adst; float* alpha;
    float* asum; float* colsum; float* attn;
};

#define SEM_SMEM  ((16384 + 64 * 132) * sizeof(float))
#define PROJ64_SMEM  ((64 * 128 + 64 * 68) * sizeof(float))
#define PROJ128_SMEM ((128 * 128 + 64 * 132) * sizeof(float))

static void run_han_layer(const float* input, const float* input2, int Kin,
                          const float* pw, const float* pb,
                          const float* att_src, const float* att_dst,
                          const float* q, const float* kw, const float* kb,
                          const int* ei0, const int* ei1, const Scratch& S) {
    if (Kin == 64) {
        proj_tf32_kernel<64, false><<<GEMM_BLOCKS, 256, PROJ64_SMEM>>>(
            input, nullptr, nullptr, pw, pb, S.h);
    } else {
        proj_tf32_kernel<128, true><<<GEMM_BLOCKS, 256, PROJ128_SMEM>>>(
            input, input2, S.attn, pw, pb, S.h);
    }

    node_attn_kernel<<<(NN * 32 + 255) / 256, 256>>>(S.h, att_src, att_dst,
                                                     S.asrc, S.adst, NN);

    cudaMemsetAsync(S.colsum, 0, MT * CC * sizeof(float));
    cudaMemsetAsync(S.asum, 0, MT * NN * HH * sizeof(float));
    cudaMemsetAsync(S.out, 0, (size_t)MT * NN * CC * sizeof(float));

    edge_softmax_both<<<(2 * EE + 255) / 256, 256>>>(ei0, ei1, S.asrc, S.adst,
                                                     S.alpha, S.asum);
    edge_message_both<<<(2 * (EE / 8) * 32 + 255) / 256, 256>>>(
        ei0, ei1, S.alpha, S.asum, S.h, S.out);
    semantic_both_kernel<<<2 * GEMM_BLOCKS, 256, SEM_SMEM>>>(
        S.out, kw, kb, S.colsum);

    score_softmax_kernel<<<1, 128>>>(q, S.colsum, S.attn);
}

extern "C" void kernel_launch(void* const* d_in, const int* in_sizes, int n_in,
                              void* d_out, int out_size) {
    const float *x = nullptr, *p1w = nullptr;
    const float *b128[6] = {nullptr};
    const float *a256[4] = {nullptr};
    const float *w16384[3] = {nullptr};
    const float *lin_w = nullptr, *lin_b = nullptr;
    const int *ei[2] = {nullptr, nullptr};
    int n128 = 0, n256 = 0, n16384 = 0, nei = 0;

    for (int i = 0; i < n_in; ++i) {
        int sz = in_sizes[i];
        const void* p = d_in[i];
        switch (sz) {
            case NN * FIN:      x = (const float*)p; break;
            case 2 * EE:        if (nei < 2) ei[nei++] = (const int*)p; break;
            case FIN * CC:      p1w = (const float*)p; break;
            case CC * CC:       if (n16384 < 3) w16384[n16384++] = (const float*)p; break;
            case MT * HH * DD:  if (n256 < 4) a256[n256++] = (const float*)p; break;
            case CC:            if (n128 < 6) b128[n128++] = (const float*)p; break;
            case CC * OUTD:     lin_w = (const float*)p; break;
            case OUTD:          lin_b = (const float*)p; break;
            default: break;
        }
    }
    const float* p1_kw = w16384[0];
    const float* p2w   = w16384[1];
    const float* p2_kw = w16384[2];
    const float *p1_pb = b128[0], *p1_q = b128[1], *p1_kb = b128[2];
    const float *p2_pb = b128[3], *p2_q = b128[4], *p2_kb = b128[5];
    const float *p1_as = a256[0], *p1_ad = a256[1];
    const float *p2_as = a256[2], *p2_ad = a256[3];

    (void)cudaFuncSetAttribute(proj_tf32_kernel<64, false>,
                               cudaFuncAttributeMaxDynamicSharedMemorySize, 110 * 1024);
    (void)cudaFuncSetAttribute(proj_tf32_kernel<128, true>,
                               cudaFuncAttributeMaxDynamicSharedMemorySize, 110 * 1024);
    (void)cudaFuncSetAttribute(semantic_both_kernel,
                               cudaFuncAttributeMaxDynamicSharedMemorySize, 110 * 1024);

    Scratch S;
    cudaGetSymbolAddress((void**)&S.h, g_h);
    cudaGetSymbolAddress((void**)&S.out, g_out);
    cudaGetSymbolAddress((void**)&S.asrc, g_asrc);
    cudaGetSymbolAddress((void**)&S.adst, g_adst);
    cudaGetSymbolAddress((void**)&S.alpha, g_alpha);
    cudaGetSymbolAddress((void**)&S.asum, g_asum);
    cudaGetSymbolAddress((void**)&S.colsum, g_colsum);
    cudaGetSymbolAddress((void**)&S.attn, g_attn);

    float* out0 = S.out;
    float* out1 = S.out + (size_t)NN * CC;

    // Layer 1: IN=64 -> C=128
    run_han_layer(x, nullptr, 64, p1w, p1_pb, p1_as, p1_ad, p1_q, p1_kw, p1_kb,
                  ei[0], ei[1], S);
    // Layer 2: combine fused into tf32 projection A-stage
    run_han_layer(out0, out1, 128, p2w, p2_pb, p2_as, p2_ad, p2_q, p2_kw,
                  p2_kb, ei[0], ei[1], S);

    // Final classifier (combine fused)
    final_linear_kernel<<<(NN * 32 + 255) / 256, 256>>>(
        out0, out1, S.attn, lin_w, lin_b, (float*)d_out);
}

// round 17
// speedup vs baseline: 1.0189x; 1.0189x over previous
#include <cuda_runtime.h>
#include <math.h>
#include <stdint.h>

// Problem constants
#define NN   100000
#define FIN  64
#define CC   128
#define HH   2
#define DD   64
#define EE   600000
#define MT   2
#define OUTD 8

// ---------------------------------------------------------------------------
// Scratch (device globals — no allocation allowed)
// ---------------------------------------------------------------------------
__device__ float    g_h[(size_t)NN * CC];
__device__ float    g_out[(size_t)MT * NN * CC];
__device__ float    g_asrc[MT * NN * HH];
__device__ float    g_adst[MT * NN * HH];
__device__ float    g_alpha[(size_t)MT * EE * HH];
__device__ float    g_asum[MT * NN * HH];
__device__ float    g_colsum[MT * CC];
__device__ float    g_attn[MT];

// ---------------------------------------------------------------------------
// Helpers
// ---------------------------------------------------------------------------
__device__ __forceinline__ float tanh_fast(float x) {
    float y;
    asm("tanh.approx.f32 %0, %1;" : "=f"(y) : "f"(x));
    return y;
}
__device__ __forceinline__ void red_add_v4(float* p, float x, float y, float z, float w) {
    asm volatile("red.global.add.v4.f32 [%0], {%1,%2,%3,%4};"
                 :: "l"(p), "f"(x), "f"(y), "f"(z), "f"(w) : "memory");
}
__device__ __forceinline__ void red_add_v2(float* p, float x, float y) {
    asm volatile("red.global.add.v2.f32 [%0], {%1,%2};"
                 :: "l"(p), "f"(x), "f"(y) : "memory");
}
__device__ __forceinline__ float f2tf32f(float f) {
    uint32_t u;
    asm("cvt.rna.tf32.f32 %0, %1;" : "=r"(u) : "f"(f));
    return __uint_as_float(u);
}
__device__ __forceinline__ void mma_tf32(float& c0, float& c1, float& c2, float& c3,
                                         uint32_t a0, uint32_t a1, uint32_t a2, uint32_t a3,
                                         uint32_t b0, uint32_t b1) {
    asm volatile(
        "mma.sync.aligned.m16n8k8.row.col.f32.tf32.tf32.f32 "
        "{%0,%1,%2,%3}, {%4,%5,%6,%7}, {%8,%9}, {%0,%1,%2,%3};"
        : "+f"(c0), "+f"(c1), "+f"(c2), "+f"(c3)
        : "r"(a0), "r"(a1), "r"(a2), "r"(a3), "r"(b0), "r"(b1));
}

// ===========================================================================
// tf32 GEMM core layout (R10/R14 validated): 64x128 tile, fragment-major W.
// ===========================================================================

// ---------------------------------------------------------------------------
// tf32 projection GEMM (R14 WIN): out[n,c] = A[n,:K] @ W[K,128] + b[c]
// FUSED (layer-2): A row := attn0*relu(o0) + attn1*relu(o1)
// ---------------------------------------------------------------------------
template <int K, bool FUSED>
__global__ void __launch_bounds__(256)
proj_tf32_kernel(const float* __restrict__ A,
                 const float* __restrict__ A2,
                 const float* __restrict__ attn,
                 const float* __restrict__ W,
                 const float* __restrict__ b,
                 float* __restrict__ out) {
    extern __shared__ float smem[];
    float* sWf = smem;
    float* sA  = smem + K * 128;
    const int tid  = threadIdx.x;
    const int lane = tid & 31;
    const int warp = tid >> 5;
    const int g4   = lane >> 2;
    const int tig  = lane & 3;
    const int rt   = warp & 3;
    const int ch   = warp >> 2;
    const int KS = K + 4;

    for (int i4 = tid; i4 < K * 32; i4 += 256) {
        int k  = i4 >> 5;
        int n0 = (i4 & 31) * 4;
        float4 w4 = ((const float4*)W)[i4];
        float wv[4] = {w4.x, w4.y, w4.z, w4.w};
        int ks = k >> 3;
        int slot = (k & 7) >> 2;
        int km = k & 3;
#pragma unroll
        for (int j = 0; j < 4; ++j) {
            int n = n0 + j;
            int nt = n >> 3;
            int ln = (n & 7) * 4 + km;
            sWf[(((ks * 16) + nt) * 32 + ln) * 2 + slot] = f2tf32f(wv[j]);
        }
    }

    float2 bv[8];
#pragma unroll
    for (int nl = 0; nl < 8; ++nl)
        bv[nl] = *(const float2*)&b[(ch * 8 + nl) * 8 + tig * 2];

    float at0 = 0.f, at1 = 0.f;
    if (FUSED) { at0 = attn[0]; at1 = attn[1]; }

    const int ntiles = (NN + 63) / 64;
    for (int tile = blockIdx.x; tile < ntiles; tile += gridDim.x) {
        __syncthreads();
        const int rowbase = tile * 64;
        const float4* Ab  = (const float4*)(A  + (size_t)rowbase * K);
        const float4* Ab2 = FUSED ? (const float4*)(A2 + (size_t)rowbase * K)
                                  : nullptr;
        for (int i4 = tid; i4 < 64 * (K / 4); i4 += 256) {
            int r = i4 / (K / 4), k4 = i4 % (K / 4);
            float4 v = make_float4(0.f, 0.f, 0.f, 0.f);
            if (rowbase + r < NN) {
                if (FUSED) {
                    float4 u = Ab[i4], w = Ab2[i4];
                    v.x = f2tf32f(at0 * fmaxf(u.x, 0.f) + at1 * fmaxf(w.x, 0.f));
                    v.y = f2tf32f(at0 * fmaxf(u.y, 0.f) + at1 * fmaxf(w.y, 0.f));
                    v.z = f2tf32f(at0 * fmaxf(u.z, 0.f) + at1 * fmaxf(w.z, 0.f));
                    v.w = f2tf32f(at0 * fmaxf(u.w, 0.f) + at1 * fmaxf(w.w, 0.f));
                } else {
                    float4 u = Ab[i4];
                    v.x = f2tf32f(u.x); v.y = f2tf32f(u.y);
                    v.z = f2tf32f(u.z); v.w = f2tf32f(u.w);
                }
            }
            float* dst = &sA[r * KS + k4 * 4];
            dst[0] = v.x; dst[1] = v.y; dst[2] = v.z; dst[3] = v.w;
        }
        __syncthreads();

        float c[8][4];
#pragma unroll
        for (int nl = 0; nl < 8; ++nl)
#pragma unroll
            for (int j = 0; j < 4; ++j) c[nl][j] = 0.0f;

        const int abase = (rt * 16 + g4) * KS;
#pragma unroll 4
        for (int ks = 0; ks < K / 8; ++ks) {
            const int k0 = ks * 8;
            uint32_t a0 = __float_as_uint(sA[abase + k0 + tig]);
            uint32_t a1 = __float_as_uint(sA[abase + 8 * KS + k0 + tig]);
            uint32_t a2 = __float_as_uint(sA[abase + k0 + 4 + tig]);
            uint32_t a3 = __float_as_uint(sA[abase + 8 * KS + k0 + 4 + tig]);
#pragma unroll
            for (int nl = 0; nl < 8; ++nl) {
                int nt = ch * 8 + nl;
                float2 bf = *(const float2*)&sWf[((ks * 16 + nt) * 32 + lane) * 2];
                mma_tf32(c[nl][0], c[nl][1], c[nl][2], c[nl][3],
                         a0, a1, a2, a3,
                         __float_as_uint(bf.x), __float_as_uint(bf.y));
            }
        }

        const int rowa = rowbase + rt * 16 + g4;
        const int rowb = rowa + 8;
#pragma unroll
        for (int nl = 0; nl < 8; ++nl) {
            int col = (ch * 8 + nl) * 8 + tig * 2;
            if (rowa < NN)
                *(float2*)&out[(size_t)rowa * 128 + col] =
                    make_float2(c[nl][0] + bv[nl].x, c[nl][1] + bv[nl].y);
            if (rowb < NN)
                *(float2*)&out[(size_t)rowb * 128 + col] =
                    make_float2(c[nl][2] + bv[nl].x, c[nl][3] + bv[nl].y);
        }
    }
}

// ---------------------------------------------------------------------------
// Semantic GEMM, tf32, BOTH edge types in one launch:
// blocks [0,296) -> type 0, [296,592) -> type 1.
// ---------------------------------------------------------------------------
#define GEMM_BLOCKS 296
#define SEM_TILES ((NN + 63) / 64)
__global__ void __launch_bounds__(256)
semantic_both_kernel(const float* __restrict__ outT,
                     const float* __restrict__ kw,
                     const float* __restrict__ kb,
                     float* __restrict__ colsum) {
    extern __shared__ float smem[];
    float* sWf = smem;
    float* sA  = smem + 16384;
    __shared__ float scol[128];
    const int tid  = threadIdx.x;
    const int lane = tid & 31;
    const int warp = tid >> 5;
    const int g4   = lane >> 2;
    const int tig  = lane & 3;
    const int rt   = warp & 3;
    const int ch   = warp >> 2;
    const int t    = blockIdx.x >= GEMM_BLOCKS;
    const float* A = outT + (size_t)t * NN * CC;
    float* cs      = colsum + t * CC;
    const int tile0 = blockIdx.x - t * GEMM_BLOCKS;

    for (int i4 = tid; i4 < 4096; i4 += 256) {
        int k  = i4 >> 5;
        int n0 = (i4 & 31) * 4;
        float4 w4 = ((const float4*)kw)[i4];
        float wv[4] = {w4.x, w4.y, w4.z, w4.w};
        int ks = k >> 3;
        int slot = (k & 7) >> 2;
        int km = k & 3;
#pragma unroll
        for (int j = 0; j < 4; ++j) {
            int n = n0 + j;
            int nt = n >> 3;
            int ln = (n & 7) * 4 + km;
            sWf[(((ks * 16) + nt) * 32 + ln) * 2 + slot] = f2tf32f(wv[j]);
        }
    }
    if (tid < 128) scol[tid] = 0.0f;

    float2 kbv[8];
#pragma unroll
    for (int nl = 0; nl < 8; ++nl)
        kbv[nl] = *(const float2*)&kb[(ch * 8 + nl) * 8 + tig * 2];

    float tloc[8][2];
#pragma unroll
    for (int nl = 0; nl < 8; ++nl) { tloc[nl][0] = 0.f; tloc[nl][1] = 0.f; }

    for (int tile = tile0; tile < SEM_TILES; tile += GEMM_BLOCKS) {
        __syncthreads();
        const int rowbase = tile * 64;
        const float4* Ab = (const float4*)(A + (size_t)rowbase * 128);
        for (int i4 = tid; i4 < 2048; i4 += 256) {
            int r = i4 >> 5, k4 = i4 & 31;
            float4 v = make_float4(0.f, 0.f, 0.f, 0.f);
            if (rowbase + r < NN) {
                float4 u = Ab[i4];
                v.x = f2tf32f(fmaxf(u.x, 0.f));
                v.y = f2tf32f(fmaxf(u.y, 0.f));
                v.z = f2tf32f(fmaxf(u.z, 0.f));
                v.w = f2tf32f(fmaxf(u.w, 0.f));
            }
            float* dst = &sA[r * 132 + k4 * 4];
            dst[0] = v.x; dst[1] = v.y; dst[2] = v.z; dst[3] = v.w;
        }
        __syncthreads();

        float c[8][4];
#pragma unroll
        for (int nl = 0; nl < 8; ++nl)
#pragma unroll
            for (int j = 0; j < 4; ++j) c[nl][j] = 0.0f;

        const int abase = (rt * 16 + g4) * 132;
#pragma unroll 4
        for (int ks = 0; ks < 16; ++ks) {
            const int k0 = ks * 8;
            uint32_t a0 = __float_as_uint(sA[abase + k0 + tig]);
            uint32_t a1 = __float_as_uint(sA[abase + 8 * 132 + k0 + tig]);
            uint32_t a2 = __float_as_uint(sA[abase + k0 + 4 + tig]);
            uint32_t a3 = __float_as_uint(sA[abase + 8 * 132 + k0 + 4 + tig]);
#pragma unroll
            for (int nl = 0; nl < 8; ++nl) {
                int nt = ch * 8 + nl;
                float2 bf = *(const float2*)&sWf[((ks * 16 + nt) * 32 + lane) * 2];
                mma_tf32(c[nl][0], c[nl][1], c[nl][2], c[nl][3],
                         a0, a1, a2, a3,
                         __float_as_uint(bf.x), __float_as_uint(bf.y));
            }
        }

        const int rowa = rowbase + rt * 16 + g4;
        const int rowb = rowa + 8;
        const bool va = rowa < NN, vb = rowb < NN;
#pragma unroll
        for (int nl = 0; nl < 8; ++nl) {
            if (va) {
                tloc[nl][0] += tanh_fast(c[nl][0] + kbv[nl].x);
                tloc[nl][1] += tanh_fast(c[nl][1] + kbv[nl].y);
            }
            if (vb) {
                tloc[nl][0] += tanh_fast(c[nl][2] + kbv[nl].x);
                tloc[nl][1] += tanh_fast(c[nl][3] + kbv[nl].y);
            }
        }
    }

#pragma unroll
    for (int nl = 0; nl < 8; ++nl) {
        int col = (ch * 8 + nl) * 8 + tig * 2;
        atomicAdd(&scol[col], tloc[nl][0]);
        atomicAdd(&scol[col + 1], tloc[nl][1]);
    }
    __syncthreads();
    if (tid < 128) atomicAdd(&cs[tid], scol[tid]);
}

// ---------------------------------------------------------------------------
// Per-node attention logits, warp per node
// ---------------------------------------------------------------------------
__global__ void node_attn_kernel(const float* __restrict__ h,
                                 const float* __restrict__ att_src,
                                 const float* __restrict__ att_dst,
                                 float* __restrict__ asrc,
                                 float* __restrict__ adst, int n) {
    int gid = blockIdx.x * blockDim.x + threadIdx.x;
    int node = gid >> 5;
    int lane = gid & 31;
    if (node >= n) return;
    const float* hrow = h + (size_t)node * CC;
    float h00 = hrow[lane];
    float h01 = hrow[lane + 32];
    float h10 = hrow[lane + 64];
    float h11 = hrow[lane + 96];

    float r[8];
#pragma unroll
    for (int t = 0; t < MT; ++t) {
        const float* as = att_src + t * CC;
        const float* ad = att_dst + t * CC;
        r[t * 4 + 0] = h00 * as[lane] + h01 * as[lane + 32];
        r[t * 4 + 1] = h10 * as[lane + 64] + h11 * as[lane + 96];
        r[t * 4 + 2] = h00 * ad[lane] + h01 * ad[lane + 32];
        r[t * 4 + 3] = h10 * ad[lane + 64] + h11 * ad[lane + 96];
    }
#pragma unroll
    for (int i = 0; i < 8; ++i) {
#pragma unroll
        for (int off = 16; off > 0; off >>= 1)
            r[i] += __shfl_xor_sync(0xffffffffu, r[i], off);
    }
    if (lane == 0) {
#pragma unroll
        for (int t = 0; t < MT; ++t) {
            asrc[t * (NN * HH) + node * HH + 0] = r[t * 4 + 0];
            asrc[t * (NN * HH) + node * HH + 1] = r[t * 4 + 1];
            adst[t * (NN * HH) + node * HH + 0] = r[t * 4 + 2];
            adst[t * (NN * HH) + node * HH + 1] = r[t * 4 + 3];
        }
    }
}

// ---------------------------------------------------------------------------
// Edge softmax, BOTH edge types in one launch (2E threads)
// ---------------------------------------------------------------------------
__global__ void edge_softmax_both(const int* __restrict__ ei0,
                                  const int* __restrict__ ei1,
                                  const float* __restrict__ asrc,
                                  const float* __restrict__ adst,
                                  float* __restrict__ alpha,
                                  float* __restrict__ asum) {
    int e2 = blockIdx.x * blockDim.x + threadIdx.x;
    if (e2 >= 2 * EE) return;
    int t = e2 >= EE;
    int e = e2 - t * EE;
    const int* ei = t ? ei1 : ei0;
    const float* as = asrc + t * (NN * HH);
    const float* ad = adst + t * (NN * HH);
    int src = ei[e];
    int dst = ei[EE + e];
    float2 s = *(const float2*)&as[src * HH];
    float2 d = *(const float2*)&ad[dst * HH];
    float a0 = s.x + d.x;
    float a1 = s.y + d.y;
    float l0 = (a0 > 0.0f) ? a0 : 0.2f * a0;
    float l1 = (a1 > 0.0f) ? a1 : 0.2f * a1;
    float ex0 = expf(l0);
    float ex1 = expf(l1);
    *(float2*)&alpha[((size_t)t * EE + e) * HH] = make_float2(ex0, ex1);
    red_add_v2(&asum[t * (NN * HH) + dst * HH], ex0, ex1);
}

// ---------------------------------------------------------------------------
// Edge message, BOTH types, 4 edges per warp (R11/R14-measured body: regs~40,
// occ~61%; 8-edge variant measured WORSE in R15 due to occupancy halving).
// ---------------------------------------------------------------------------
__global__ void edge_message_both(const int* __restrict__ ei0,
                                  const int* __restrict__ ei1,
                                  const float* __restrict__ alpha,
                                  const float* __restrict__ asum,
                                  const float* __restrict__ h,
                                  float* __restrict__ outT) {
    int gid = blockIdx.x * blockDim.x + threadIdx.x;
    int w = gid >> 5;
    int lane = gid & 31;
    const int WPT = EE / 4;              // warps per type
    if (w >= 2 * WPT) return;
    int t = w >= WPT;
    int wl = w - t * WPT;
    const int* ei = t ? ei1 : ei0;
    const float* al = alpha + (size_t)t * EE * HH;
    const float* su = asum + t * (NN * HH);
    float* ot = outT + (size_t)t * NN * CC;
    const int e0 = wl * 4;
    const int head = lane >> 4;

    int4 s4 = ((const int4*)ei)[wl];
    int4 d4 = ((const int4*)ei)[EE / 4 + wl];
    int srcs[4] = {s4.x, s4.y, s4.z, s4.w};
    int dsts[4] = {d4.x, d4.y, d4.z, d4.w};

    float av[4], sv[4];
#pragma unroll
    for (int i = 0; i < 4; ++i)
        av[i] = al[(size_t)(e0 + i) * HH + head];
#pragma unroll
    for (int i = 0; i < 4; ++i)
        sv[i] = su[dsts[i] * HH + head];

    float4 v[4];
#pragma unroll
    for (int i = 0; i < 4; ++i)
        v[i] = ((const float4*)(h + (size_t)srcs[i] * CC))[lane];

#pragma unroll
    for (int i = 0; i < 4; ++i) {
        float coef = av[i] / (sv[i] + 1e-16f);
        float* o = ot + (size_t)dsts[i] * CC + lane * 4;
        red_add_v4(o, v[i].x * coef, v[i].y * coef, v[i].z * coef, v[i].w * coef);
    }
}

// ---------------------------------------------------------------------------
// Semantic score + softmax (single block, 128 threads)
// ---------------------------------------------------------------------------
__global__ void score_softmax_kernel(const float* __restrict__ q,
                                     const float* __restrict__ colsum,
                                     float* __restrict__ attn) {
    __shared__ float red[128];
    int c = threadIdx.x;
    float s[MT];
#pragma unroll
    for (int m = 0; m < MT; ++m) {
        red[c] = q[c] * colsum[m * CC + c];
        __syncthreads();
        for (int off = 64; off > 0; off >>= 1) {
            if (c < off) red[c] += red[c + off];
            __syncthreads();
        }
        s[m] = red[0] * (1.0f / (float)NN);
        __syncthreads();
    }
    if (c == 0) {
        float mx = fmaxf(s[0], s[1]);
        float e0 = expf(s[0] - mx), e1 = expf(s[1] - mx);
        float inv = 1.0f / (e0 + e1);
        attn[0] = e0 * inv;
        attn[1] = e1 * inv;
    }
}

// ---------------------------------------------------------------------------
// Final linear fused with combine: warp per node
// ---------------------------------------------------------------------------
__global__ void final_linear_kernel(const float* __restrict__ o0,
                                    const float* __restrict__ o1,
                                    const float* __restrict__ attn,
                                    const float* __restrict__ lw,
                                    const float* __restrict__ lb,
                                    float* __restrict__ out) {
    int gid = blockIdx.x * blockDim.x + threadIdx.x;
    int node = gid >> 5;
    int lane = gid & 31;
    if (node >= NN) return;
    float a0 = attn[0], a1 = attn[1];
    float4 u = ((const float4*)(o0 + (size_t)node * CC))[lane];
    float4 v = ((const float4*)(o1 + (size_t)node * CC))[lane];
    float c0 = a0 * fmaxf(u.x, 0.f) + a1 * fmaxf(v.x, 0.f);
    float c1 = a0 * fmaxf(u.y, 0.f) + a1 * fmaxf(v.y, 0.f);
    float c2 = a0 * fmaxf(u.z, 0.f) + a1 * fmaxf(v.z, 0.f);
    float c3 = a0 * fmaxf(u.w, 0.f) + a1 * fmaxf(v.w, 0.f);
    const float* w = lw + lane * 4 * OUTD;
#pragma unroll
    for (int o = 0; o < OUTD; ++o) {
        float p = c0 * w[o] + c1 * w[OUTD + o] + c2 * w[2 * OUTD + o]
                + c3 * w[3 * OUTD + o];
#pragma unroll
        for (int off = 16; off > 0; off >>= 1)
            p += __shfl_xor_sync(0xffffffffu, p, off);
        if (lane == 0) out[(size_t)node * OUTD + o] = p + lb[o];
    }
}

// ---------------------------------------------------------------------------
// Host side
// ---------------------------------------------------------------------------
struct Scratch {
    float* h; float* out;
    float* asrc; float* adst; float* alpha;
    float* asum; float* colsum; float* attn;
};

#define SEM_SMEM  ((16384 + 64 * 132) * sizeof(float))
#define PROJ64_SMEM  ((64 * 128 + 64 * 68) * sizeof(float))
#define PROJ128_SMEM ((128 * 128 + 64 * 132) * sizeof(float))

static void run_han_layer(const float* input, const float* input2, int Kin,
                          const float* pw, const float* pb,
                          const float* att_src, const float* att_dst,
                          const float* q, const float* kw, const float* kb,
                          const int* ei0, const int* ei1, const Scratch& S) {
    if (Kin == 64) {
        proj_tf32_kernel<64, false><<<GEMM_BLOCKS, 256, PROJ64_SMEM>>>(
            input, nullptr, nullptr, pw, pb, S.h);
    } else {
        proj_tf32_kernel<128, true><<<GEMM_BLOCKS, 256, PROJ128_SMEM>>>(
            input, input2, S.attn, pw, pb, S.h);
    }

    node_attn_kernel<<<(NN * 32 + 255) / 256, 256>>>(S.h, att_src, att_dst,
                                                     S.asrc, S.adst, NN);

    cudaMemsetAsync(S.colsum, 0, MT * CC * sizeof(float));
    cudaMemsetAsync(S.asum, 0, MT * NN * HH * sizeof(float));
    cudaMemsetAsync(S.out, 0, (size_t)MT * NN * CC * sizeof(float));

    edge_softmax_both<<<(2 * EE + 255) / 256, 256>>>(ei0, ei1, S.asrc, S.adst,
                                                     S.alpha, S.asum);
    edge_message_both<<<(2 * (EE / 4) * 32 + 255) / 256, 256>>>(
        ei0, ei1, S.alpha, S.asum, S.h, S.out);
    semantic_both_kernel<<<2 * GEMM_BLOCKS, 256, SEM_SMEM>>>(
        S.out, kw, kb, S.colsum);

    score_softmax_kernel<<<1, 128>>>(q, S.colsum, S.attn);
}

extern "C" void kernel_launch(void* const* d_in, const int* in_sizes, int n_in,
                              void* d_out, int out_size) {
    const float *x = nullptr, *p1w = nullptr;
    const float *b128[6] = {nullptr};
    const float *a256[4] = {nullptr};
    const float *w16384[3] = {nullptr};
    const float *lin_w = nullptr, *lin_b = nullptr;
    const int *ei[2] = {nullptr, nullptr};
    int n128 = 0, n256 = 0, n16384 = 0, nei = 0;

    for (int i = 0; i < n_in; ++i) {
        int sz = in_sizes[i];
        const void* p = d_in[i];
        switch (sz) {
            case NN * FIN:      x = (const float*)p; break;
            case 2 * EE:        if (nei < 2) ei[nei++] = (const int*)p; break;
            case FIN * CC:      p1w = (const float*)p; break;
            case CC * CC:       if (n16384 < 3) w16384[n16384++] = (const float*)p; break;
            case MT * HH * DD:  if (n256 < 4) a256[n256++] = (const float*)p; break;
            case CC:            if (n128 < 6) b128[n128++] = (const float*)p; break;
            case CC * OUTD:     lin_w = (const float*)p; break;
            case OUTD:          lin_b = (const float*)p; break;
            default: break;
        }
    }
    const float* p1_kw = w16384[0];
    const float* p2w   = w16384[1];
    const float* p2_kw = w16384[2];
    const float *p1_pb = b128[0], *p1_q = b128[1], *p1_kb = b128[2];
    const float *p2_pb = b128[3], *p2_q = b128[4], *p2_kb = b128[5];
    const float *p1_as = a256[0], *p1_ad = a256[1];
    const float *p2_as = a256[2], *p2_ad = a256[3];

    (void)cudaFuncSetAttribute(proj_tf32_kernel<64, false>,
                               cudaFuncAttributeMaxDynamicSharedMemorySize, 110 * 1024);
    (void)cudaFuncSetAttribute(proj_tf32_kernel<128, true>,
                               cudaFuncAttributeMaxDynamicSharedMemorySize, 110 * 1024);
    (void)cudaFuncSetAttribute(semantic_both_kernel,
                               cudaFuncAttributeMaxDynamicSharedMemorySize, 110 * 1024);

    Scratch S;
    cudaGetSymbolAddress((void**)&S.h, g_h);
    cudaGetSymbolAddress((void**)&S.out, g_out);
    cudaGetSymbolAddress((void**)&S.asrc, g_asrc);
    cudaGetSymbolAddress((void**)&S.adst, g_adst);
    cudaGetSymbolAddress((void**)&S.alpha, g_alpha);
    cudaGetSymbolAddress((void**)&S.asum, g_asum);
    cudaGetSymbolAddress((void**)&S.colsum, g_colsum);
    cudaGetSymbolAddress((void**)&S.attn, g_attn);

    float* out0 = S.out;
    float* out1 = S.out + (size_t)NN * CC;

    // Layer 1: IN=64 -> C=128
    run_han_layer(x, nullptr, 64, p1w, p1_pb, p1_as, p1_ad, p1_q, p1_kw, p1_kb,
                  ei[0], ei[1], S);
    // Layer 2: combine fused into tf32 projection A-stage
    run_han_layer(out0, out1, 128, p2w, p2_pb, p2_as, p2_ad, p2_q, p2_kw,
                  p2_kb, ei[0], ei[1], S);

    // Final classifier (combine fused)
    final_linear_kernel<<<(NN * 32 + 255) / 256, 256>>>(
        out0, out1, S.attn, lin_w, lin_b, (float*)d_out);
}